// round 15
// baseline (speedup 1.0000x reference)
#include <cuda_runtime.h>
#include <cuda_bf16.h>
#include <math.h>
#include <cstdint>

#define NB 256
#define NR 36
#define NL 40
#define ND 1024
#define MT (NB * NR)   /* 9216  */
#define NT (NB * NL)   /* 10240 */
#define EPSF 1e-8f
#define LAMS 9.0f

#define MROWS 9472     /* 9216 img rows + 256 pool_img */
#define NROWS 10496    /* 10240 cap rows + 256 pool_txt */

// ---- scratch (device globals; no allocation allowed) ----
__device__ float g_S[(size_t)MT * NT];           // S^T[n][m], leaky-relu'd (378MB)
__device__ __nv_bfloat16 g_Ah[(size_t)MROWS * ND];  // bf16 img_emb ++ pool_img
__device__ __nv_bfloat16 g_Bh[(size_t)NROWS * ND];  // bf16 cap_emb ++ pool_txt
__device__ float g_P[NB * NB * NR];
__device__ float g_Q[NB * NB * NL];
__device__ float g_G[NB * NR * NR];
__device__ float g_H[NB * NL * NL];
__device__ float g_base[NB * NB];
__device__ float g_w1i[NB];
__device__ float g_w1t[NB];

__device__ __forceinline__ float4 ldg4(const float* p) {
    return *reinterpret_cast<const float4*>(p);
}
__device__ __forceinline__ float4 ldg4cs(const float* p) {
    return __ldcs(reinterpret_cast<const float4*>(p));
}
__device__ __forceinline__ uint32_t pack_bf2(float x, float y) {
    __nv_bfloat162 h = __float22bfloat162_rn(make_float2(x, y));
    return *reinterpret_cast<uint32_t*>(&h);
}
__device__ __forceinline__ void mma_bf16(float* c, const uint32_t* a, const uint32_t* b) {
    asm volatile(
        "mma.sync.aligned.m16n8k16.row.col.f32.bf16.bf16.f32 "
        "{%0,%1,%2,%3}, {%4,%5,%6,%7}, {%8,%9}, {%0,%1,%2,%3};"
        : "+f"(c[0]), "+f"(c[1]), "+f"(c[2]), "+f"(c[3])
        : "r"(a[0]), "r"(a[1]), "r"(a[2]), "r"(a[3]), "r"(b[0]), "r"(b[1]));
}
__device__ __forceinline__ void cpa16(uint32_t saddr, const void* gaddr) {
    asm volatile("cp.async.ca.shared.global [%0], [%1], 16;"
                 :: "r"(saddr), "l"(gaddr) : "memory");
}
__device__ __forceinline__ void ldsm_x4(uint32_t& r0, uint32_t& r1, uint32_t& r2,
                                        uint32_t& r3, uint32_t addr) {
    asm volatile("ldmatrix.sync.aligned.m8n8.x4.shared.b16 {%0,%1,%2,%3}, [%4];"
                 : "=r"(r0), "=r"(r1), "=r"(r2), "=r"(r3) : "r"(addr));
}

// ============================ bf16 conversion (augmented operands) ============================
__global__ void cvt_kernel(const float* __restrict__ img, const float* __restrict__ pimg,
                           const float* __restrict__ cap, const float* __restrict__ ptxt) {
    size_t g8 = (size_t)blockIdx.x * 256 + threadIdx.x;
    const size_t A8 = (size_t)MROWS * (ND / 8);
    const float* src;
    uint32_t* dst;
    if (g8 < A8) {
        size_t off = g8 * 8;
        size_t row = off >> 10, col = off & 1023;
        src = (row < 9216) ? (img + row * ND + col) : (pimg + (row - 9216) * ND + col);
        dst = reinterpret_cast<uint32_t*>(g_Ah) + g8 * 4;
    } else {
        size_t h8 = g8 - A8;
        size_t off = h8 * 8;
        size_t row = off >> 10, col = off & 1023;
        src = (row < 10240) ? (cap + row * ND + col) : (ptxt + (row - 10240) * ND + col);
        dst = reinterpret_cast<uint32_t*>(g_Bh) + h8 * 4;
    }
    float4 x = ldg4(src), y = ldg4(src + 4);
    *reinterpret_cast<uint4*>(dst) =
        make_uint4(pack_bf2(x.x, x.y), pack_bf2(x.z, x.w),
                   pack_bf2(y.x, y.y), pack_bf2(y.z, y.w));
}

// ============================ precompute kernels ============================
__global__ void norm_kernel(const float* __restrict__ pi, const float* __restrict__ pt) {
    int w = blockIdx.x * 8 + (threadIdx.x >> 5);
    int lane = threadIdx.x & 31;
    const float* src = (w < NB) ? (pi + (size_t)w * ND) : (pt + (size_t)(w - NB) * ND);
    float s = 0.f;
    for (int j = lane; j < ND; j += 32) { float v = src[j]; s = fmaf(v, v, s); }
#pragma unroll
    for (int o = 16; o; o >>= 1) s += __shfl_down_sync(0xffffffffu, s, o);
    if (lane == 0) {
        float r = sqrtf(s);
        if (w < NB) g_w1i[w] = r; else g_w1t[w - NB] = r;
    }
}

__global__ void sgemm_tn(const float* __restrict__ A, const float* __restrict__ Bm,
                         int M, int N, int K) {
    float* C = g_base;
    __shared__ float As[16 * 64];
    __shared__ float Bs[16 * 64];
    int tid = threadIdx.x;
    int tx = tid & 15, ty = tid >> 4;
    int m0 = blockIdx.y * 64, n0 = blockIdx.x * 64;
    int row = tid >> 2, q = tid & 3;
    float acc[4][4] = {};
    for (int k0 = 0; k0 < K; k0 += 16) {
        float4 a = ldg4(A + (size_t)(m0 + row) * K + k0 + q * 4);
        float4 bb = ldg4(Bm + (size_t)(n0 + row) * K + k0 + q * 4);
        As[(q * 4 + 0) * 64 + row] = a.x;  As[(q * 4 + 1) * 64 + row] = a.y;
        As[(q * 4 + 2) * 64 + row] = a.z;  As[(q * 4 + 3) * 64 + row] = a.w;
        Bs[(q * 4 + 0) * 64 + row] = bb.x; Bs[(q * 4 + 1) * 64 + row] = bb.y;
        Bs[(q * 4 + 2) * 64 + row] = bb.z; Bs[(q * 4 + 3) * 64 + row] = bb.w;
        __syncthreads();
#pragma unroll
        for (int k = 0; k < 16; k++) {
            float4 av = *(const float4*)(As + k * 64 + ty * 4);
            float4 bv = *(const float4*)(Bs + k * 64 + tx * 4);
            float aa[4] = {av.x, av.y, av.z, av.w};
            float bw[4] = {bv.x, bv.y, bv.z, bv.w};
#pragma unroll
            for (int ii = 0; ii < 4; ii++)
#pragma unroll
                for (int jj = 0; jj < 4; jj++)
                    acc[ii][jj] = fmaf(aa[ii], bw[jj], acc[ii][jj]);
        }
        __syncthreads();
    }
#pragma unroll
    for (int ii = 0; ii < 4; ii++)
#pragma unroll
        for (int jj = 0; jj < 4; jj++)
            C[(size_t)(m0 + ty * 4 + ii) * N + n0 + tx * 4 + jj] = acc[ii][jj];
}

// per-row Gram, 4x4 register-blocked, symmetric
__global__ void gram_kernel(const float* __restrict__ emb, int ROWS, int which) {
    extern __shared__ float Es[];
    float* out = which ? g_H : g_G;
    int b = blockIdx.x, tid = threadIdx.x;
    int wid = tid >> 5, lane = tid & 31;
    int n = ROWS * ND;
    int np = ROWS * ROWS;
    for (int idx = tid; idx < n; idx += 256) Es[idx] = emb[(size_t)b * n + idx];
    __syncthreads();
    int nt4 = ROWS / 4;
    int count = nt4 * (nt4 + 1) / 2;
    for (int p = wid; p < count; p += 8) {
        int pl = p, tr = 0;
        while (pl >= nt4 - tr) { pl -= nt4 - tr; tr++; }
        int tc = tr + pl;
        const float* E1 = Es + (size_t)tr * 4 * ND;
        const float* E2 = Es + (size_t)tc * 4 * ND;
        float acc[4][4] = {};
        for (int kk = 0; kk < ND; kk += 32) {
            int k = kk + lane;
            float e1[4], e2[4];
#pragma unroll
            for (int j = 0; j < 4; j++) { e1[j] = E1[j * ND + k]; e2[j] = E2[j * ND + k]; }
#pragma unroll
            for (int j = 0; j < 4; j++)
#pragma unroll
                for (int jj = 0; jj < 4; jj++)
                    acc[j][jj] = fmaf(e1[j], e2[jj], acc[j][jj]);
        }
#pragma unroll
        for (int j = 0; j < 4; j++)
#pragma unroll
            for (int jj = 0; jj < 4; jj++) {
#pragma unroll
                for (int o = 16; o; o >>= 1)
                    acc[j][jj] += __shfl_xor_sync(0xffffffffu, acc[j][jj], o);
            }
        if (lane == 0) {
#pragma unroll
            for (int j = 0; j < 4; j++)
#pragma unroll
                for (int jj = 0; jj < 4; jj++) {
                    float v = acc[j][jj];
                    out[(size_t)b * np + (tr * 4 + j) * ROWS + tc * 4 + jj] = v;
                    out[(size_t)b * np + (tc * 4 + jj) * ROWS + tr * 4 + j] = v;
                }
        }
    }
}

// ============================ bf16 cp.async GEMM: BK=64, 3 stages (R14 proven) ============================
#define BM 128
#define BN 256
#define BK 64
#define ASZW (BM * 36)              /* 4608 words */
#define STGW (ASZW + BN * 36)       /* 13824 words = 55296 B */
#define STAGES 3
#define GEMM_SMEM (STAGES * STGW * 4)   /* 165888 B */

__global__ void __launch_bounds__(256, 1) s_gemm(const __nv_bfloat16* __restrict__ Ah,
                                                 const __nv_bfloat16* __restrict__ Bh,
                                                 float* __restrict__ S) {
    extern __shared__ uint32_t smw[];
    uint32_t sb;
    asm("{ .reg .u64 t; cvta.to.shared.u64 t, %1; cvt.u32.u64 %0, t; }" : "=r"(sb) : "l"(smw));
    const int tid = threadIdx.x;
    const int wid = tid >> 5;
    const int lane = tid & 31;
    const int g = lane >> 2;
    const int t = lane & 3;
    const int wm = wid >> 2;
    const int wn = wid & 3;
    const int by = blockIdx.y;
    const int bx = blockIdx.x;
    const int m0 = by * BM;
    const int n0 = bx * BN;
    const bool pBlk = (bx == 40);
    const bool qBlk = (by >= 72);

    const int r0 = tid >> 3;
    const int c0 = tid & 7;
    const __nv_bfloat16* Agp = (qBlk ? (Ah + (size_t)9216 * ND + (size_t)(by - 72) * BM * ND)
                                     : (Ah + (size_t)m0 * ND)) + (size_t)r0 * ND + c0 * 8;
    const __nv_bfloat16* Bgp = (pBlk ? (Bh + (size_t)10240 * ND)
                                     : (Bh + (size_t)n0 * ND)) + (size_t)r0 * ND + c0 * 8;
    const uint32_t sA = sb + (uint32_t)(r0 * 144 + c0 * 16);
    const uint32_t sB = sb + (uint32_t)(ASZW * 4 + r0 * 144 + c0 * 16);

    const int alr = (lane & 7) + ((lane >> 3) & 1) * 8;
    const int ahf = (lane >> 4) & 1;
    const int blr = (lane & 7) + ((lane >> 4) & 1) * 8;
    const int bhf = (lane >> 3) & 1;
    const uint32_t aFrag = sb + (uint32_t)((wm * 64 + alr) * 144 + ahf * 16);
    const uint32_t bFrag = sb + (uint32_t)(ASZW * 4 + (wn * 64 + blr) * 144 + bhf * 16);

    float cacc[4][8][4];
#pragma unroll
    for (int a = 0; a < 4; a++)
#pragma unroll
        for (int bb = 0; bb < 8; bb++)
#pragma unroll
            for (int cc = 0; cc < 4; cc++) cacc[a][bb][cc] = 0.f;

#define ISSUE(stg, kc) do {                                                    \
    uint32_t so = (uint32_t)(stg) * (STGW * 4);                                \
    _Pragma("unroll")                                                          \
    for (int j = 0; j < 4; j++)                                                \
        cpa16(sA + so + j * (32 * 144), Agp + (size_t)j * 32 * ND + (kc));     \
    _Pragma("unroll")                                                          \
    for (int j = 0; j < 8; j++)                                                \
        cpa16(sB + so + j * (32 * 144), Bgp + (size_t)j * 32 * ND + (kc));     \
} while (0)

#define COMPUTE(stg, ks) do {                                                  \
    const uint32_t so = (uint32_t)(stg) * (STGW * 4) + (ks) * 32;              \
    uint32_t af[4][4];                                                         \
    uint32_t bf[8][2];                                                         \
    _Pragma("unroll")                                                          \
    for (int mt = 0; mt < 4; mt++)                                             \
        ldsm_x4(af[mt][0], af[mt][1], af[mt][2], af[mt][3],                    \
                aFrag + so + mt * (16 * 144));                                 \
    _Pragma("unroll")                                                          \
    for (int np = 0; np < 4; np++)                                             \
        ldsm_x4(bf[2 * np][0], bf[2 * np][1], bf[2 * np + 1][0],               \
                bf[2 * np + 1][1], bFrag + so + np * (16 * 144));              \
    _Pragma("unroll")                                                          \
    for (int mt = 0; mt < 4; mt++)                                             \
        _Pragma("unroll")                                                      \
        for (int nt = 0; nt < 8; nt++)                                         \
            mma_bf16(cacc[mt][nt], af[mt], bf[nt]);                            \
} while (0)

    ISSUE(0, 0);  asm volatile("cp.async.commit_group;" ::: "memory");
    ISSUE(1, 64); asm volatile("cp.async.commit_group;" ::: "memory");

#pragma unroll 1
    for (int c = 0; c < 16; c++) {
        asm volatile("cp.async.wait_group 1;" ::: "memory");
        __syncthreads();
        int st = c % 3;
        COMPUTE(st, 0);
        COMPUTE(st, 1);
        COMPUTE(st, 2);
        COMPUTE(st, 3);
        if (c < 14) ISSUE((c + 2) % 3, (c + 2) * BK);
        asm volatile("cp.async.commit_group;" ::: "memory");
    }

    if (pBlk && qBlk) return;

    if (!pBlk && !qBlk) {
#pragma unroll
        for (int mt = 0; mt < 4; mt++) {
            int m = m0 + wm * 64 + mt * 16 + g;
#pragma unroll
            for (int nt = 0; nt < 8; nt++) {
                int n = n0 + wn * 64 + nt * 8 + 2 * t;
                float v0 = cacc[mt][nt][0]; v0 = (v0 >= 0.f) ? v0 : 0.1f * v0;
                float v1 = cacc[mt][nt][1]; v1 = (v1 >= 0.f) ? v1 : 0.1f * v1;
                float v2 = cacc[mt][nt][2]; v2 = (v2 >= 0.f) ? v2 : 0.1f * v2;
                float v3 = cacc[mt][nt][3]; v3 = (v3 >= 0.f) ? v3 : 0.1f * v3;
                __stcs(S + (size_t)n * MT + m, v0);
                __stcs(S + (size_t)(n + 1) * MT + m, v1);
                __stcs(S + (size_t)n * MT + m + 8, v2);
                __stcs(S + (size_t)(n + 1) * MT + m + 8, v3);
            }
        }
    } else if (pBlk) {
#pragma unroll
        for (int mt = 0; mt < 4; mt++) {
            int m = m0 + wm * 64 + mt * 16 + g;
#pragma unroll
            for (int nt = 0; nt < 8; nt++) {
                int i = wn * 64 + nt * 8 + 2 * t;
                __stcs(g_P + (size_t)i * MT + m, cacc[mt][nt][0]);
                __stcs(g_P + (size_t)(i + 1) * MT + m, cacc[mt][nt][1]);
                __stcs(g_P + (size_t)i * MT + m + 8, cacc[mt][nt][2]);
                __stcs(g_P + (size_t)(i + 1) * MT + m + 8, cacc[mt][nt][3]);
            }
        }
    } else {
#pragma unroll
        for (int mt = 0; mt < 4; mt++) {
            int b = (by - 72) * BM + wm * 64 + mt * 16 + g;
#pragma unroll
            for (int nt = 0; nt < 8; nt++) {
                int n = n0 + wn * 64 + nt * 8 + 2 * t;
                __stcs(g_Q + (size_t)b * NT + n, cacc[mt][nt][0]);
                __stcs(g_Q + (size_t)b * NT + n + 1, cacc[mt][nt][1]);
                __stcs(g_Q + (size_t)(b + 8) * NT + n, cacc[mt][nt][2]);
                __stcs(g_Q + (size_t)(b + 8) * NT + n + 1, cacc[mt][nt][3]);
            }
        }
    }
#undef ISSUE
#undef COMPUTE
}

// ============================ per-pair epilogue: 192 threads, single task round ============================
// word offsets: FS 0 (40x37=1480, [l][r]) | Am 1480 (40x44) | Cm 3240 (36x44)
//               Hs 4824 (40x40) | Gs 6424 (36x36) | w2p1 7720 (40x9) | w2p2 8080 (36x10)
#define EPI_WORDS 8440
#define EPI_SMEM (EPI_WORDS * 4)
#define ETH 192

__global__ void __launch_bounds__(ETH) pair_epilogue(const float* __restrict__ S,
                                                     float* __restrict__ out) {
    extern __shared__ float sh[];
    __shared__ float Pb[NR], Qi[NL], rnl[NR], cnl[NL], s1s[NL], s2s[NR];
    float* FS = sh;          // [l][r] stride 37
    float* Am = sh + 1480;
    float* Cm = sh + 3240;
    float* Hs = sh + 4824;
    float* Gs = sh + 6424;
    float* w2p1 = sh + 7720;
    float* w2p2 = sh + 8080;
    const int i = blockIdx.x, b = blockIdx.y, tid = threadIdx.x;

    // --- vectorized global loads (low MLP_p1; S streamed with .cs) ---
    const float* Sp = S + (size_t)i * NL * MT + (size_t)b * NR;
    for (int q = tid; q < 360; q += ETH) {
        int l = q / 9, sg = q - l * 9;
        float4 v = ldg4cs(Sp + (size_t)l * MT + sg * 4);
        float* d = FS + l * 37 + sg * 4;
        d[0] = v.x; d[1] = v.y; d[2] = v.z; d[3] = v.w;
    }
    {
        const float4* Gg = (const float4*)(g_G + (size_t)b * (NR * NR));
        for (int q = tid; q < 324; q += ETH) ((float4*)Gs)[q] = Gg[q];
        const float4* Hg = (const float4*)(g_H + (size_t)i * (NL * NL));
        for (int q = tid; q < 400; q += ETH) ((float4*)Hs)[q] = Hg[q];
    }
    if (tid < 9) {
        float4 v = ldg4(g_P + (size_t)i * MT + b * NR + tid * 4);
        Pb[tid * 4 + 0] = v.x; Pb[tid * 4 + 1] = v.y;
        Pb[tid * 4 + 2] = v.z; Pb[tid * 4 + 3] = v.w;
    } else if (tid >= 64 && tid < 74) {
        int q = tid - 64;
        float4 v = ldg4(g_Q + (size_t)b * NT + i * NL + q * 4);
        Qi[q * 4 + 0] = v.x; Qi[q * 4 + 1] = v.y;
        Qi[q * 4 + 2] = v.z; Qi[q * 4 + 3] = v.w;
    }
    __syncthreads();

    if (tid < NL) {
        int l = tid; float s = 0.f;
#pragma unroll
        for (int r = 0; r < NR; r++) { float v = FS[l * 37 + r]; s = fmaf(v, v, s); }
        cnl[l] = LAMS / (sqrtf(s) + EPSF);
    } else if (tid >= 64 && tid < 64 + NR) {
        int r = tid - 64; float s = 0.f;
#pragma unroll
        for (int l = 0; l < NL; l++) { float v = FS[l * 37 + r]; s = fmaf(v, v, s); }
        rnl[r] = LAMS / (sqrtf(s) + EPSF);
    }
    __syncthreads();

    for (int idx = tid; idx < NR * NL; idx += ETH) {
        int l = idx / NR, r = idx - l * NR;
        float v = FS[l * 37 + r];
        Am[l * 44 + r] = __expf(v * rnl[r]);
        Cm[r * 44 + l] = __expf(v * cnl[l]);
    }
    __syncthreads();

    // fused mini-GEMM + quadratic form: 180 tasks, single round over 192 threads
    if (tid < 180) {
        int task = tid;
        float4 acc0 = make_float4(0.f, 0.f, 0.f, 0.f);
        float4 acc1 = acc0, acc2 = acc0, acc3 = acc0;
        float4 st0 = acc0, st1 = acc0, st2 = acc0, st3 = acc0;
        if (task < 90) {
            int lg = task / 9, rg = task - lg * 9;
            const float* Ab = Am + lg * 4 * 44;
            const float* Gb = Gs + rg * 4;
#pragma unroll
            for (int rp4 = 0; rp4 < 9; rp4++) {
                float4 a0 = *(const float4*)(Ab + rp4 * 4);
                float4 a1 = *(const float4*)(Ab + 44 + rp4 * 4);
                float4 a2 = *(const float4*)(Ab + 88 + rp4 * 4);
                float4 a3 = *(const float4*)(Ab + 132 + rp4 * 4);
                if (rp4 == rg) { st0 = a0; st1 = a1; st2 = a2; st3 = a3; }
                float4 g0 = *(const float4*)(Gb + (rp4 * 4 + 0) * 36);
                float4 g1 = *(const float4*)(Gb + (rp4 * 4 + 1) * 36);
                float4 g2 = *(const float4*)(Gb + (rp4 * 4 + 2) * 36);
                float4 g3 = *(const float4*)(Gb + (rp4 * 4 + 3) * 36);
#define ACC4(ACC, AV)                                                          \
                ACC.x = fmaf(AV.x, g0.x, ACC.x); ACC.y = fmaf(AV.x, g0.y, ACC.y); \
                ACC.z = fmaf(AV.x, g0.z, ACC.z); ACC.w = fmaf(AV.x, g0.w, ACC.w); \
                ACC.x = fmaf(AV.y, g1.x, ACC.x); ACC.y = fmaf(AV.y, g1.y, ACC.y); \
                ACC.z = fmaf(AV.y, g1.z, ACC.z); ACC.w = fmaf(AV.y, g1.w, ACC.w); \
                ACC.x = fmaf(AV.z, g2.x, ACC.x); ACC.y = fmaf(AV.z, g2.y, ACC.y); \
                ACC.z = fmaf(AV.z, g2.z, ACC.z); ACC.w = fmaf(AV.z, g2.w, ACC.w); \
                ACC.x = fmaf(AV.w, g3.x, ACC.x); ACC.y = fmaf(AV.w, g3.y, ACC.y); \
                ACC.z = fmaf(AV.w, g3.z, ACC.z); ACC.w = fmaf(AV.w, g3.w, ACC.w);
                ACC4(acc0, a0) ACC4(acc1, a1) ACC4(acc2, a2) ACC4(acc3, a3)
            }
            int l = lg * 4;
            w2p1[(l + 0) * 9 + rg] = acc0.x * st0.x + acc0.y * st0.y + acc0.z * st0.z + acc0.w * st0.w;
            w2p1[(l + 1) * 9 + rg] = acc1.x * st1.x + acc1.y * st1.y + acc1.z * st1.z + acc1.w * st1.w;
            w2p1[(l + 2) * 9 + rg] = acc2.x * st2.x + acc2.y * st2.y + acc2.z * st2.z + acc2.w * st2.w;
            w2p1[(l + 3) * 9 + rg] = acc3.x * st3.x + acc3.y * st3.y + acc3.z * st3.z + acc3.w * st3.w;
        } else {
            int t2 = task - 90;
            int rg = t2 / 10, lg = t2 - rg * 10;
            const float* Cb = Cm + rg * 4 * 44;
            const float* Hb = Hs + lg * 4;
#pragma unroll
            for (int lp4 = 0; lp4 < 10; lp4++) {
                float4 a0 = *(const float4*)(Cb + lp4 * 4);
                float4 a1 = *(const float4*)(Cb + 44 + lp4 * 4);
                float4 a2 = *(const float4*)(Cb + 88 + lp4 * 4);
                float4 a3 = *(const float4*)(Cb + 132 + lp4 * 4);
                if (lp4 == lg) { st0 = a0; st1 = a1; st2 = a2; st3 = a3; }
                float4 g0 = *(const float4*)(Hb + (lp4 * 4 + 0) * 40);
                float4 g1 = *(const float4*)(Hb + (lp4 * 4 + 1) * 40);
                float4 g2 = *(const float4*)(Hb + (lp4 * 4 + 2) * 40);
                float4 g3 = *(const float4*)(Hb + (lp4 * 4 + 3) * 40);
                ACC4(acc0, a0) ACC4(acc1, a1) ACC4(acc2, a2) ACC4(acc3, a3)
#undef ACC4
            }
            int r = rg * 4;
            w2p2[(r + 0) * 10 + lg] = acc0.x * st0.x + acc0.y * st0.y + acc0.z * st0.z + acc0.w * st0.w;
            w2p2[(r + 1) * 10 + lg] = acc1.x * st1.x + acc1.y * st1.y + acc1.z * st1.z + acc1.w * st1.w;
            w2p2[(r + 2) * 10 + lg] = acc2.x * st2.x + acc2.y * st2.y + acc2.z * st2.z + acc2.w * st2.w;
            w2p2[(r + 3) * 10 + lg] = acc3.x * st3.x + acc3.y * st3.y + acc3.z * st3.z + acc3.w * st3.w;
        }
    }
    __syncthreads();

    if (tid < NL) {
        int l = tid; float w12 = 0.f, w2 = 0.f;
#pragma unroll
        for (int r = 0; r < NR; r++) w12 = fmaf(Am[l * 44 + r], Pb[r], w12);
#pragma unroll
        for (int k = 0; k < 9; k++) w2 += w2p1[l * 9 + k];
        float den = fmaxf(g_w1t[i] * sqrtf(fmaxf(w2, 0.f)), EPSF);
        s1s[l] = __fdividef(w12, den);
    } else if (tid >= 64 && tid < 64 + NR) {
        int r = tid - 64; float w12 = 0.f, w2 = 0.f;
#pragma unroll
        for (int l = 0; l < NL; l++) w12 = fmaf(Cm[r * 44 + l], Qi[l], w12);
#pragma unroll
        for (int k = 0; k < 10; k++) w2 += w2p2[r * 10 + k];
        float den = fmaxf(g_w1i[b] * sqrtf(fmaxf(w2, 0.f)), EPSF);
        s2s[r] = __fdividef(w12, den);
    }
    __syncthreads();

    if (tid == 0) {
        float m1 = 0.f, m2 = 0.f;
#pragma unroll
        for (int l = 0; l < NL; l++) m1 += s1s[l];
#pragma unroll
        for (int r = 0; r < NR; r++) m2 += s2s[r];
        out[(size_t)b * NB + i] = g_base[b * NB + i] + m1 * (1.f / NL) + m2 * (1.f / NR);
    }
}

// ============================ launch ============================
extern "C" void kernel_launch(void* const* d_in, const int* in_sizes, int n_in,
                              void* d_out, int out_size) {
    (void)in_sizes; (void)n_in; (void)out_size;
    const float* pool_img = (const float*)d_in[0];
    const float* img_emb  = (const float*)d_in[1];
    const float* pool_txt = (const float*)d_in[2];
    const float* cap_emb  = (const float*)d_in[3];
    float* out = (float*)d_out;

    cudaFuncSetAttribute((const void*)gram_kernel,
                         cudaFuncAttributeMaxDynamicSharedMemorySize, NL * ND * 4);
    cudaFuncSetAttribute((const void*)s_gemm,
                         cudaFuncAttributeMaxDynamicSharedMemorySize, GEMM_SMEM);
    cudaFuncSetAttribute((const void*)pair_epilogue,
                         cudaFuncAttributeMaxDynamicSharedMemorySize, EPI_SMEM);

    float* dS = nullptr;
    cudaGetSymbolAddress((void**)&dS, g_S);
    __nv_bfloat16* dAh = nullptr; cudaGetSymbolAddress((void**)&dAh, g_Ah);
    __nv_bfloat16* dBh = nullptr; cudaGetSymbolAddress((void**)&dBh, g_Bh);

    // order: s_gemm stays at launch index 3 (profiled slot)
    cvt_kernel<<<9984, 256>>>(img_emb, pool_img, cap_emb, pool_txt);
    gram_kernel<<<NB, 256, NR * ND * 4>>>(img_emb, NR, 0);
    gram_kernel<<<NB, 256, NL * ND * 4>>>(cap_emb, NL, 1);
    s_gemm<<<dim3(41, 74), 256, GEMM_SMEM>>>(dAh, dBh, dS);
    norm_kernel<<<64, 256>>>(pool_img, pool_txt);
    sgemm_tn<<<dim3(NB / 64, NB / 64), 256>>>(pool_img, pool_txt, NB, NB, ND);
    pair_epilogue<<<dim3(NB, NB), ETH, EPI_SMEM>>>(dS, out);
}

// round 16
// speedup vs baseline: 1.0666x; 1.0666x over previous
#include <cuda_runtime.h>
#include <cuda_bf16.h>
#include <math.h>
#include <cstdint>

#define NB 256
#define NR 36
#define NL 40
#define ND 1024
#define MT (NB * NR)   /* 9216  */
#define NT (NB * NL)   /* 10240 */
#define EPSF 1e-8f
#define LAMS 9.0f

#define MROWS 9472     /* 9216 img rows + 256 pool_img */
#define NROWS 10496    /* 10240 cap rows + 256 pool_txt */

// ---- scratch (device globals; no allocation allowed) ----
__device__ float g_S[(size_t)MT * NT];           // S^T[n][m], leaky-relu'd (378MB)
__device__ __nv_bfloat16 g_Ah[(size_t)MROWS * ND];  // bf16 img_emb ++ pool_img
__device__ __nv_bfloat16 g_Bh[(size_t)NROWS * ND];  // bf16 cap_emb ++ pool_txt
__device__ float g_P[NB * NB * NR];
__device__ float g_Q[NB * NB * NL];
__device__ float g_G[NB * NR * NR];
__device__ float g_H[NB * NL * NL];
__device__ float g_base[NB * NB];
__device__ float g_w1i[NB];
__device__ float g_w1t[NB];

__device__ __forceinline__ float4 ldg4(const float* p) {
    return *reinterpret_cast<const float4*>(p);
}
__device__ __forceinline__ uint32_t pack_bf2(float x, float y) {
    __nv_bfloat162 h = __float22bfloat162_rn(make_float2(x, y));
    return *reinterpret_cast<uint32_t*>(&h);
}
__device__ __forceinline__ void mma_bf16(float* c, const uint32_t* a, const uint32_t* b) {
    asm volatile(
        "mma.sync.aligned.m16n8k16.row.col.f32.bf16.bf16.f32 "
        "{%0,%1,%2,%3}, {%4,%5,%6,%7}, {%8,%9}, {%0,%1,%2,%3};"
        : "+f"(c[0]), "+f"(c[1]), "+f"(c[2]), "+f"(c[3])
        : "r"(a[0]), "r"(a[1]), "r"(a[2]), "r"(a[3]), "r"(b[0]), "r"(b[1]));
}
__device__ __forceinline__ void cpa16(uint32_t saddr, const void* gaddr) {
    asm volatile("cp.async.ca.shared.global [%0], [%1], 16;"
                 :: "r"(saddr), "l"(gaddr) : "memory");
}
__device__ __forceinline__ void ldsm_x4(uint32_t& r0, uint32_t& r1, uint32_t& r2,
                                        uint32_t& r3, uint32_t addr) {
    asm volatile("ldmatrix.sync.aligned.m8n8.x4.shared.b16 {%0,%1,%2,%3}, [%4];"
                 : "=r"(r0), "=r"(r1), "=r"(r2), "=r"(r3) : "r"(addr));
}

// ============================ bf16 conversion (augmented operands) ============================
__global__ void cvt_kernel(const float* __restrict__ img, const float* __restrict__ pimg,
                           const float* __restrict__ cap, const float* __restrict__ ptxt) {
    size_t g8 = (size_t)blockIdx.x * 256 + threadIdx.x;
    const size_t A8 = (size_t)MROWS * (ND / 8);
    const float* src;
    uint32_t* dst;
    if (g8 < A8) {
        size_t off = g8 * 8;
        size_t row = off >> 10, col = off & 1023;
        src = (row < 9216) ? (img + row * ND + col) : (pimg + (row - 9216) * ND + col);
        dst = reinterpret_cast<uint32_t*>(g_Ah) + g8 * 4;
    } else {
        size_t h8 = g8 - A8;
        size_t off = h8 * 8;
        size_t row = off >> 10, col = off & 1023;
        src = (row < 10240) ? (cap + row * ND + col) : (ptxt + (row - 10240) * ND + col);
        dst = reinterpret_cast<uint32_t*>(g_Bh) + h8 * 4;
    }
    float4 x = ldg4(src), y = ldg4(src + 4);
    *reinterpret_cast<uint4*>(dst) =
        make_uint4(pack_bf2(x.x, x.y), pack_bf2(x.z, x.w),
                   pack_bf2(y.x, y.y), pack_bf2(y.z, y.w));
}

// ============================ precompute kernels ============================
__global__ void norm_kernel(const float* __restrict__ pi, const float* __restrict__ pt) {
    int w = blockIdx.x * 8 + (threadIdx.x >> 5);
    int lane = threadIdx.x & 31;
    const float* src = (w < NB) ? (pi + (size_t)w * ND) : (pt + (size_t)(w - NB) * ND);
    float s = 0.f;
    for (int j = lane; j < ND; j += 32) { float v = src[j]; s = fmaf(v, v, s); }
#pragma unroll
    for (int o = 16; o; o >>= 1) s += __shfl_down_sync(0xffffffffu, s, o);
    if (lane == 0) {
        float r = sqrtf(s);
        if (w < NB) g_w1i[w] = r; else g_w1t[w - NB] = r;
    }
}

__global__ void sgemm_tn(const float* __restrict__ A, const float* __restrict__ Bm,
                         int M, int N, int K) {
    float* C = g_base;
    __shared__ float As[16 * 64];
    __shared__ float Bs[16 * 64];
    int tid = threadIdx.x;
    int tx = tid & 15, ty = tid >> 4;
    int m0 = blockIdx.y * 64, n0 = blockIdx.x * 64;
    int row = tid >> 2, q = tid & 3;
    float acc[4][4] = {};
    for (int k0 = 0; k0 < K; k0 += 16) {
        float4 a = ldg4(A + (size_t)(m0 + row) * K + k0 + q * 4);
        float4 bb = ldg4(Bm + (size_t)(n0 + row) * K + k0 + q * 4);
        As[(q * 4 + 0) * 64 + row] = a.x;  As[(q * 4 + 1) * 64 + row] = a.y;
        As[(q * 4 + 2) * 64 + row] = a.z;  As[(q * 4 + 3) * 64 + row] = a.w;
        Bs[(q * 4 + 0) * 64 + row] = bb.x; Bs[(q * 4 + 1) * 64 + row] = bb.y;
        Bs[(q * 4 + 2) * 64 + row] = bb.z; Bs[(q * 4 + 3) * 64 + row] = bb.w;
        __syncthreads();
#pragma unroll
        for (int k = 0; k < 16; k++) {
            float4 av = *(const float4*)(As + k * 64 + ty * 4);
            float4 bv = *(const float4*)(Bs + k * 64 + tx * 4);
            float aa[4] = {av.x, av.y, av.z, av.w};
            float bw[4] = {bv.x, bv.y, bv.z, bv.w};
#pragma unroll
            for (int ii = 0; ii < 4; ii++)
#pragma unroll
                for (int jj = 0; jj < 4; jj++)
                    acc[ii][jj] = fmaf(aa[ii], bw[jj], acc[ii][jj]);
        }
        __syncthreads();
    }
#pragma unroll
    for (int ii = 0; ii < 4; ii++)
#pragma unroll
        for (int jj = 0; jj < 4; jj++)
            C[(size_t)(m0 + ty * 4 + ii) * N + n0 + tx * 4 + jj] = acc[ii][jj];
}

// per-row Gram, 4x4 register-blocked, symmetric
__global__ void gram_kernel(const float* __restrict__ emb, int ROWS, int which) {
    extern __shared__ float Es[];
    float* out = which ? g_H : g_G;
    int b = blockIdx.x, tid = threadIdx.x;
    int wid = tid >> 5, lane = tid & 31;
    int n = ROWS * ND;
    int np = ROWS * ROWS;
    for (int idx = tid; idx < n; idx += 256) Es[idx] = emb[(size_t)b * n + idx];
    __syncthreads();
    int nt4 = ROWS / 4;
    int count = nt4 * (nt4 + 1) / 2;
    for (int p = wid; p < count; p += 8) {
        int pl = p, tr = 0;
        while (pl >= nt4 - tr) { pl -= nt4 - tr; tr++; }
        int tc = tr + pl;
        const float* E1 = Es + (size_t)tr * 4 * ND;
        const float* E2 = Es + (size_t)tc * 4 * ND;
        float acc[4][4] = {};
        for (int kk = 0; kk < ND; kk += 32) {
            int k = kk + lane;
            float e1[4], e2[4];
#pragma unroll
            for (int j = 0; j < 4; j++) { e1[j] = E1[j * ND + k]; e2[j] = E2[j * ND + k]; }
#pragma unroll
            for (int j = 0; j < 4; j++)
#pragma unroll
                for (int jj = 0; jj < 4; jj++)
                    acc[j][jj] = fmaf(e1[j], e2[jj], acc[j][jj]);
        }
#pragma unroll
        for (int j = 0; j < 4; j++)
#pragma unroll
            for (int jj = 0; jj < 4; jj++) {
#pragma unroll
                for (int o = 16; o; o >>= 1)
                    acc[j][jj] += __shfl_xor_sync(0xffffffffu, acc[j][jj], o);
            }
        if (lane == 0) {
#pragma unroll
            for (int j = 0; j < 4; j++)
#pragma unroll
                for (int jj = 0; jj < 4; jj++) {
                    float v = acc[j][jj];
                    out[(size_t)b * np + (tr * 4 + j) * ROWS + tc * 4 + jj] = v;
                    out[(size_t)b * np + (tc * 4 + jj) * ROWS + tr * 4 + j] = v;
                }
        }
    }
}

// ============================ bf16 cp.async GEMM: BK=64, 4 stages, 3-deep prefetch ============================
#define BM 128
#define BN 256
#define BK 64
#define ASZW (BM * 36)              /* 4608 words */
#define STGW (ASZW + BN * 36)       /* 13824 words = 55296 B */
#define STAGES 4
#define GEMM_SMEM (STAGES * STGW * 4)   /* 221184 B */

__global__ void __launch_bounds__(256, 1) s_gemm(const __nv_bfloat16* __restrict__ Ah,
                                                 const __nv_bfloat16* __restrict__ Bh,
                                                 float* __restrict__ S) {
    extern __shared__ uint32_t smw[];
    uint32_t sb;
    asm("{ .reg .u64 t; cvta.to.shared.u64 t, %1; cvt.u32.u64 %0, t; }" : "=r"(sb) : "l"(smw));
    const int tid = threadIdx.x;
    const int wid = tid >> 5;
    const int lane = tid & 31;
    const int g = lane >> 2;
    const int t = lane & 3;
    const int wm = wid >> 2;
    const int wn = wid & 3;
    const int by = blockIdx.y;
    const int bx = blockIdx.x;
    const int m0 = by * BM;
    const int n0 = bx * BN;
    const bool pBlk = (bx == 40);
    const bool qBlk = (by >= 72);

    const int r0 = tid >> 3;
    const int c0 = tid & 7;
    const __nv_bfloat16* Agp = (qBlk ? (Ah + (size_t)9216 * ND + (size_t)(by - 72) * BM * ND)
                                     : (Ah + (size_t)m0 * ND)) + (size_t)r0 * ND + c0 * 8;
    const __nv_bfloat16* Bgp = (pBlk ? (Bh + (size_t)10240 * ND)
                                     : (Bh + (size_t)n0 * ND)) + (size_t)r0 * ND + c0 * 8;
    const uint32_t sA = sb + (uint32_t)(r0 * 144 + c0 * 16);
    const uint32_t sB = sb + (uint32_t)(ASZW * 4 + r0 * 144 + c0 * 16);

    const int alr = (lane & 7) + ((lane >> 3) & 1) * 8;
    const int ahf = (lane >> 4) & 1;
    const int blr = (lane & 7) + ((lane >> 4) & 1) * 8;
    const int bhf = (lane >> 3) & 1;
    const uint32_t aFrag = sb + (uint32_t)((wm * 64 + alr) * 144 + ahf * 16);
    const uint32_t bFrag = sb + (uint32_t)(ASZW * 4 + (wn * 64 + blr) * 144 + bhf * 16);

    float cacc[4][8][4];
#pragma unroll
    for (int a = 0; a < 4; a++)
#pragma unroll
        for (int bb = 0; bb < 8; bb++)
#pragma unroll
            for (int cc = 0; cc < 4; cc++) cacc[a][bb][cc] = 0.f;

#define ISSUE(stg, kc) do {                                                    \
    uint32_t so = (uint32_t)(stg) * (STGW * 4);                                \
    _Pragma("unroll")                                                          \
    for (int j = 0; j < 4; j++)                                                \
        cpa16(sA + so + j * (32 * 144), Agp + (size_t)j * 32 * ND + (kc));     \
    _Pragma("unroll")                                                          \
    for (int j = 0; j < 8; j++)                                                \
        cpa16(sB + so + j * (32 * 144), Bgp + (size_t)j * 32 * ND + (kc));     \
} while (0)

#define COMPUTE(stg, ks) do {                                                  \
    const uint32_t so = (uint32_t)(stg) * (STGW * 4) + (ks) * 32;              \
    uint32_t af[4][4];                                                         \
    uint32_t bf[8][2];                                                         \
    _Pragma("unroll")                                                          \
    for (int mt = 0; mt < 4; mt++)                                             \
        ldsm_x4(af[mt][0], af[mt][1], af[mt][2], af[mt][3],                    \
                aFrag + so + mt * (16 * 144));                                 \
    _Pragma("unroll")                                                          \
    for (int np = 0; np < 4; np++)                                             \
        ldsm_x4(bf[2 * np][0], bf[2 * np][1], bf[2 * np + 1][0],               \
                bf[2 * np + 1][1], bFrag + so + np * (16 * 144));              \
    _Pragma("unroll")                                                          \
    for (int mt = 0; mt < 4; mt++)                                             \
        _Pragma("unroll")                                                      \
        for (int nt = 0; nt < 8; nt++)                                         \
            mma_bf16(cacc[mt][nt], af[mt], bf[nt]);                            \
} while (0)

    ISSUE(0, 0);   asm volatile("cp.async.commit_group;" ::: "memory");
    ISSUE(1, 64);  asm volatile("cp.async.commit_group;" ::: "memory");
    ISSUE(2, 128); asm volatile("cp.async.commit_group;" ::: "memory");

#pragma unroll 1
    for (int c = 0; c < 16; c++) {
        asm volatile("cp.async.wait_group 2;" ::: "memory");
        __syncthreads();
        int st = c & 3;
        COMPUTE(st, 0);
        COMPUTE(st, 1);
        COMPUTE(st, 2);
        COMPUTE(st, 3);
        if (c < 13) ISSUE((c + 3) & 3, (c + 3) * BK);
        asm volatile("cp.async.commit_group;" ::: "memory");
    }

    if (pBlk && qBlk) return;

    if (!pBlk && !qBlk) {
#pragma unroll
        for (int mt = 0; mt < 4; mt++) {
            int m = m0 + wm * 64 + mt * 16 + g;
#pragma unroll
            for (int nt = 0; nt < 8; nt++) {
                int n = n0 + wn * 64 + nt * 8 + 2 * t;
                float v0 = cacc[mt][nt][0]; v0 = (v0 >= 0.f) ? v0 : 0.1f * v0;
                float v1 = cacc[mt][nt][1]; v1 = (v1 >= 0.f) ? v1 : 0.1f * v1;
                float v2 = cacc[mt][nt][2]; v2 = (v2 >= 0.f) ? v2 : 0.1f * v2;
                float v3 = cacc[mt][nt][3]; v3 = (v3 >= 0.f) ? v3 : 0.1f * v3;
                __stcs(S + (size_t)n * MT + m, v0);
                __stcs(S + (size_t)(n + 1) * MT + m, v1);
                __stcs(S + (size_t)n * MT + m + 8, v2);
                __stcs(S + (size_t)(n + 1) * MT + m + 8, v3);
            }
        }
    } else if (pBlk) {
#pragma unroll
        for (int mt = 0; mt < 4; mt++) {
            int m = m0 + wm * 64 + mt * 16 + g;
#pragma unroll
            for (int nt = 0; nt < 8; nt++) {
                int i = wn * 64 + nt * 8 + 2 * t;
                __stcs(g_P + (size_t)i * MT + m, cacc[mt][nt][0]);
                __stcs(g_P + (size_t)(i + 1) * MT + m, cacc[mt][nt][1]);
                __stcs(g_P + (size_t)i * MT + m + 8, cacc[mt][nt][2]);
                __stcs(g_P + (size_t)(i + 1) * MT + m + 8, cacc[mt][nt][3]);
            }
        }
    } else {
#pragma unroll
        for (int mt = 0; mt < 4; mt++) {
            int b = (by - 72) * BM + wm * 64 + mt * 16 + g;
#pragma unroll
            for (int nt = 0; nt < 8; nt++) {
                int n = n0 + wn * 64 + nt * 8 + 2 * t;
                __stcs(g_Q + (size_t)b * NT + n, cacc[mt][nt][0]);
                __stcs(g_Q + (size_t)b * NT + n + 1, cacc[mt][nt][1]);
                __stcs(g_Q + (size_t)(b + 8) * NT + n, cacc[mt][nt][2]);
                __stcs(g_Q + (size_t)(b + 8) * NT + n + 1, cacc[mt][nt][3]);
            }
        }
    }
#undef ISSUE
#undef COMPUTE
}

// ============================ per-pair epilogue (R14 proven version, verbatim) ============================
// word offsets: FS 0 (40x37=1480, [l][r]) | Am 1480 (40x44) | Cm 3240 (36x44)
//               Hs 4824 (40x40) | Gs 6424 (36x36) | w2p1 7720 (40x9) | w2p2 8080 (36x10)
#define EPI_WORDS 8440
#define EPI_SMEM (EPI_WORDS * 4)

__global__ void __launch_bounds__(128) pair_epilogue(const float* __restrict__ S,
                                                     float* __restrict__ out) {
    extern __shared__ float sh[];
    __shared__ float Pb[NR], Qi[NL], rnl[NR], cnl[NL], s1s[NL], s2s[NR];
    float* FS = sh;          // [l][r] stride 37
    float* Am = sh + 1480;
    float* Cm = sh + 3240;
    float* Hs = sh + 4824;
    float* Gs = sh + 6424;
    float* w2p1 = sh + 7720;
    float* w2p2 = sh + 8080;
    const int i = blockIdx.x, b = blockIdx.y, tid = threadIdx.x;

    // --- vectorized global loads (low MLP_p1) ---
    const float* Sp = S + (size_t)i * NL * MT + (size_t)b * NR;
    for (int q = tid; q < 360; q += 128) {
        int l = q / 9, sg = q - l * 9;
        float4 v = ldg4(Sp + (size_t)l * MT + sg * 4);
        float* d = FS + l * 37 + sg * 4;
        d[0] = v.x; d[1] = v.y; d[2] = v.z; d[3] = v.w;
    }
    {
        const float4* Gg = (const float4*)(g_G + (size_t)b * (NR * NR));
        for (int q = tid; q < 324; q += 128) ((float4*)Gs)[q] = Gg[q];
        const float4* Hg = (const float4*)(g_H + (size_t)i * (NL * NL));
        for (int q = tid; q < 400; q += 128) ((float4*)Hs)[q] = Hg[q];
    }
    if (tid < 9) {
        float4 v = ldg4(g_P + (size_t)i * MT + b * NR + tid * 4);
        Pb[tid * 4 + 0] = v.x; Pb[tid * 4 + 1] = v.y;
        Pb[tid * 4 + 2] = v.z; Pb[tid * 4 + 3] = v.w;
    } else if (tid >= 64 && tid < 74) {
        int q = tid - 64;
        float4 v = ldg4(g_Q + (size_t)b * NT + i * NL + q * 4);
        Qi[q * 4 + 0] = v.x; Qi[q * 4 + 1] = v.y;
        Qi[q * 4 + 2] = v.z; Qi[q * 4 + 3] = v.w;
    }
    __syncthreads();

    if (tid < NL) {
        int l = tid; float s = 0.f;
#pragma unroll
        for (int r = 0; r < NR; r++) { float v = FS[l * 37 + r]; s = fmaf(v, v, s); }
        cnl[l] = LAMS / (sqrtf(s) + EPSF);
    } else if (tid >= 64 && tid < 64 + NR) {
        int r = tid - 64; float s = 0.f;
#pragma unroll
        for (int l = 0; l < NL; l++) { float v = FS[l * 37 + r]; s = fmaf(v, v, s); }
        rnl[r] = LAMS / (sqrtf(s) + EPSF);
    }
    __syncthreads();

    for (int idx = tid; idx < NR * NL; idx += 128) {
        int l = idx / NR, r = idx - l * NR;
        float v = FS[l * 37 + r];
        Am[l * 44 + r] = __expf(v * rnl[r]);
        Cm[r * 44 + l] = __expf(v * cnl[l]);
    }
    __syncthreads();

    // fused mini-GEMM + quadratic form: 180 tasks, each a 4x4 tile
    for (int task = tid; task < 180; task += 128) {
        float4 acc0 = make_float4(0.f, 0.f, 0.f, 0.f);
        float4 acc1 = acc0, acc2 = acc0, acc3 = acc0;
        float4 st0 = acc0, st1 = acc0, st2 = acc0, st3 = acc0;
        if (task < 90) {
            int lg = task / 9, rg = task - lg * 9;
            const float* Ab = Am + lg * 4 * 44;
            const float* Gb = Gs + rg * 4;
#pragma unroll
            for (int rp4 = 0; rp4 < 9; rp4++) {
                float4 a0 = *(const float4*)(Ab + rp4 * 4);
                float4 a1 = *(const float4*)(Ab + 44 + rp4 * 4);
                float4 a2 = *(const float4*)(Ab + 88 + rp4 * 4);
                float4 a3 = *(const float4*)(Ab + 132 + rp4 * 4);
                if (rp4 == rg) { st0 = a0; st1 = a1; st2 = a2; st3 = a3; }
                float4 g0 = *(const float4*)(Gb + (rp4 * 4 + 0) * 36);
                float4 g1 = *(const float4*)(Gb + (rp4 * 4 + 1) * 36);
                float4 g2 = *(const float4*)(Gb + (rp4 * 4 + 2) * 36);
                float4 g3 = *(const float4*)(Gb + (rp4 * 4 + 3) * 36);
#define ACC4(ACC, AV)                                                          \
                ACC.x = fmaf(AV.x, g0.x, ACC.x); ACC.y = fmaf(AV.x, g0.y, ACC.y); \
                ACC.z = fmaf(AV.x, g0.z, ACC.z); ACC.w = fmaf(AV.x, g0.w, ACC.w); \
                ACC.x = fmaf(AV.y, g1.x, ACC.x); ACC.y = fmaf(AV.y, g1.y, ACC.y); \
                ACC.z = fmaf(AV.y, g1.z, ACC.z); ACC.w = fmaf(AV.y, g1.w, ACC.w); \
                ACC.x = fmaf(AV.z, g2.x, ACC.x); ACC.y = fmaf(AV.z, g2.y, ACC.y); \
                ACC.z = fmaf(AV.z, g2.z, ACC.z); ACC.w = fmaf(AV.z, g2.w, ACC.w); \
                ACC.x = fmaf(AV.w, g3.x, ACC.x); ACC.y = fmaf(AV.w, g3.y, ACC.y); \
                ACC.z = fmaf(AV.w, g3.z, ACC.z); ACC.w = fmaf(AV.w, g3.w, ACC.w);
                ACC4(acc0, a0) ACC4(acc1, a1) ACC4(acc2, a2) ACC4(acc3, a3)
            }
            int l = lg * 4;
            w2p1[(l + 0) * 9 + rg] = acc0.x * st0.x + acc0.y * st0.y + acc0.z * st0.z + acc0.w * st0.w;
            w2p1[(l + 1) * 9 + rg] = acc1.x * st1.x + acc1.y * st1.y + acc1.z * st1.z + acc1.w * st1.w;
            w2p1[(l + 2) * 9 + rg] = acc2.x * st2.x + acc2.y * st2.y + acc2.z * st2.z + acc2.w * st2.w;
            w2p1[(l + 3) * 9 + rg] = acc3.x * st3.x + acc3.y * st3.y + acc3.z * st3.z + acc3.w * st3.w;
        } else {
            int t2 = task - 90;
            int rg = t2 / 10, lg = t2 - rg * 10;
            const float* Cb = Cm + rg * 4 * 44;
            const float* Hb = Hs + lg * 4;
#pragma unroll
            for (int lp4 = 0; lp4 < 10; lp4++) {
                float4 a0 = *(const float4*)(Cb + lp4 * 4);
                float4 a1 = *(const float4*)(Cb + 44 + lp4 * 4);
                float4 a2 = *(const float4*)(Cb + 88 + lp4 * 4);
                float4 a3 = *(const float4*)(Cb + 132 + lp4 * 4);
                if (lp4 == lg) { st0 = a0; st1 = a1; st2 = a2; st3 = a3; }
                float4 g0 = *(const float4*)(Hb + (lp4 * 4 + 0) * 40);
                float4 g1 = *(const float4*)(Hb + (lp4 * 4 + 1) * 40);
                float4 g2 = *(const float4*)(Hb + (lp4 * 4 + 2) * 40);
                float4 g3 = *(const float4*)(Hb + (lp4 * 4 + 3) * 40);
                ACC4(acc0, a0) ACC4(acc1, a1) ACC4(acc2, a2) ACC4(acc3, a3)
#undef ACC4
            }
            int r = rg * 4;
            w2p2[(r + 0) * 10 + lg] = acc0.x * st0.x + acc0.y * st0.y + acc0.z * st0.z + acc0.w * st0.w;
            w2p2[(r + 1) * 10 + lg] = acc1.x * st1.x + acc1.y * st1.y + acc1.z * st1.z + acc1.w * st1.w;
            w2p2[(r + 2) * 10 + lg] = acc2.x * st2.x + acc2.y * st2.y + acc2.z * st2.z + acc2.w * st2.w;
            w2p2[(r + 3) * 10 + lg] = acc3.x * st3.x + acc3.y * st3.y + acc3.z * st3.z + acc3.w * st3.w;
        }
    }
    __syncthreads();

    if (tid < NL) {
        int l = tid; float w12 = 0.f, w2 = 0.f;
#pragma unroll
        for (int r = 0; r < NR; r++) w12 = fmaf(Am[l * 44 + r], Pb[r], w12);
#pragma unroll
        for (int k = 0; k < 9; k++) w2 += w2p1[l * 9 + k];
        float den = fmaxf(g_w1t[i] * sqrtf(fmaxf(w2, 0.f)), EPSF);
        s1s[l] = __fdividef(w12, den);
    } else if (tid >= 64 && tid < 64 + NR) {
        int r = tid - 64; float w12 = 0.f, w2 = 0.f;
#pragma unroll
        for (int l = 0; l < NL; l++) w12 = fmaf(Cm[r * 44 + l], Qi[l], w12);
#pragma unroll
        for (int k = 0; k < 10; k++) w2 += w2p2[r * 10 + k];
        float den = fmaxf(g_w1i[b] * sqrtf(fmaxf(w2, 0.f)), EPSF);
        s2s[r] = __fdividef(w12, den);
    }
    __syncthreads();

    if (tid == 0) {
        float m1 = 0.f, m2 = 0.f;
#pragma unroll
        for (int l = 0; l < NL; l++) m1 += s1s[l];
#pragma unroll
        for (int r = 0; r < NR; r++) m2 += s2s[r];
        out[(size_t)b * NB + i] = g_base[b * NB + i] + m1 * (1.f / NL) + m2 * (1.f / NR);
    }
}

// ============================ launch ============================
extern "C" void kernel_launch(void* const* d_in, const int* in_sizes, int n_in,
                              void* d_out, int out_size) {
    (void)in_sizes; (void)n_in; (void)out_size;
    const float* pool_img = (const float*)d_in[0];
    const float* img_emb  = (const float*)d_in[1];
    const float* pool_txt = (const float*)d_in[2];
    const float* cap_emb  = (const float*)d_in[3];
    float* out = (float*)d_out;

    cudaFuncSetAttribute((const void*)gram_kernel,
                         cudaFuncAttributeMaxDynamicSharedMemorySize, NL * ND * 4);
    cudaFuncSetAttribute((const void*)s_gemm,
                         cudaFuncAttributeMaxDynamicSharedMemorySize, GEMM_SMEM);
    cudaFuncSetAttribute((const void*)pair_epilogue,
                         cudaFuncAttributeMaxDynamicSharedMemorySize, EPI_SMEM);

    float* dS = nullptr;
    cudaGetSymbolAddress((void**)&dS, g_S);
    __nv_bfloat16* dAh = nullptr; cudaGetSymbolAddress((void**)&dAh, g_Ah);
    __nv_bfloat16* dBh = nullptr; cudaGetSymbolAddress((void**)&dBh, g_Bh);

    // order: s_gemm stays at launch index 3 (profiled slot)
    cvt_kernel<<<9984, 256>>>(img_emb, pool_img, cap_emb, pool_txt);
    gram_kernel<<<NB, 256, NR * ND * 4>>>(img_emb, NR, 0);
    gram_kernel<<<NB, 256, NL * ND * 4>>>(cap_emb, NL, 1);
    s_gemm<<<dim3(41, 74), 256, GEMM_SMEM>>>(dAh, dBh, dS);
    norm_kernel<<<64, 256>>>(pool_img, pool_txt);
    sgemm_tn<<<dim3(NB / 64, NB / 64), 256>>>(pool_img, pool_txt, NB, NB, ND);
    pair_epilogue<<<dim3(NB, NB), 128, EPI_SMEM>>>(dS, out);
}

// round 17
// speedup vs baseline: 1.1009x; 1.0322x over previous
#include <cuda_runtime.h>
#include <cuda_bf16.h>
#include <math.h>
#include <cstdint>

#define NB 256
#define NR 36
#define NL 40
#define ND 1024
#define MT (NB * NR)   /* 9216  */
#define NT (NB * NL)   /* 10240 */
#define EPSF 1e-8f
#define LAMS 9.0f

#define MROWS 9472     /* 9216 img rows + 256 pool_img */
#define NROWS 10496    /* 10240 cap rows + 256 pool_txt */

// ---- scratch (device globals; no allocation allowed) ----
__device__ float g_S[(size_t)MT * NT];           // S^T[n][m], leaky-relu'd (378MB)
__device__ __nv_bfloat16 g_Ah[(size_t)MROWS * ND];  // bf16 img_emb ++ pool_img
__device__ __nv_bfloat16 g_Bh[(size_t)NROWS * ND];  // bf16 cap_emb ++ pool_txt
__device__ float g_P[NB * NB * NR];
__device__ float g_Q[NB * NB * NL];
__device__ float g_G[NB * NR * NR];
__device__ float g_H[NB * NL * NL];
__device__ float g_base[NB * NB];
__device__ float g_w1i[NB];
__device__ float g_w1t[NB];

__device__ __forceinline__ float4 ldg4(const float* p) {
    return *reinterpret_cast<const float4*>(p);
}
__device__ __forceinline__ uint32_t pack_bf2(float x, float y) {
    __nv_bfloat162 h = __float22bfloat162_rn(make_float2(x, y));
    return *reinterpret_cast<uint32_t*>(&h);
}
__device__ __forceinline__ void mma_bf16(float* c, const uint32_t* a, const uint32_t* b) {
    asm volatile(
        "mma.sync.aligned.m16n8k16.row.col.f32.bf16.bf16.f32 "
        "{%0,%1,%2,%3}, {%4,%5,%6,%7}, {%8,%9}, {%0,%1,%2,%3};"
        : "+f"(c[0]), "+f"(c[1]), "+f"(c[2]), "+f"(c[3])
        : "r"(a[0]), "r"(a[1]), "r"(a[2]), "r"(a[3]), "r"(b[0]), "r"(b[1]));
}
__device__ __forceinline__ void cpa16(uint32_t saddr, const void* gaddr) {
    asm volatile("cp.async.ca.shared.global [%0], [%1], 16;"
                 :: "r"(saddr), "l"(gaddr) : "memory");
}
__device__ __forceinline__ void ldsm_x4(uint32_t& r0, uint32_t& r1, uint32_t& r2,
                                        uint32_t& r3, uint32_t addr) {
    asm volatile("ldmatrix.sync.aligned.m8n8.x4.shared.b16 {%0,%1,%2,%3}, [%4];"
                 : "=r"(r0), "=r"(r1), "=r"(r2), "=r"(r3) : "r"(addr));
}

// ============================ bf16 conversion (augmented operands) ============================
__global__ void cvt_kernel(const float* __restrict__ img, const float* __restrict__ pimg,
                           const float* __restrict__ cap, const float* __restrict__ ptxt) {
    size_t g8 = (size_t)blockIdx.x * 256 + threadIdx.x;
    const size_t A8 = (size_t)MROWS * (ND / 8);
    const float* src;
    uint32_t* dst;
    if (g8 < A8) {
        size_t off = g8 * 8;
        size_t row = off >> 10, col = off & 1023;
        src = (row < 9216) ? (img + row * ND + col) : (pimg + (row - 9216) * ND + col);
        dst = reinterpret_cast<uint32_t*>(g_Ah) + g8 * 4;
    } else {
        size_t h8 = g8 - A8;
        size_t off = h8 * 8;
        size_t row = off >> 10, col = off & 1023;
        src = (row < 10240) ? (cap + row * ND + col) : (ptxt + (row - 10240) * ND + col);
        dst = reinterpret_cast<uint32_t*>(g_Bh) + h8 * 4;
    }
    float4 x = ldg4(src), y = ldg4(src + 4);
    *reinterpret_cast<uint4*>(dst) =
        make_uint4(pack_bf2(x.x, x.y), pack_bf2(x.z, x.w),
                   pack_bf2(y.x, y.y), pack_bf2(y.z, y.w));
}

// ============================ precompute kernels ============================
__global__ void norm_kernel(const float* __restrict__ pi, const float* __restrict__ pt) {
    int w = blockIdx.x * 8 + (threadIdx.x >> 5);
    int lane = threadIdx.x & 31;
    const float* src = (w < NB) ? (pi + (size_t)w * ND) : (pt + (size_t)(w - NB) * ND);
    float s = 0.f;
    for (int j = lane; j < ND; j += 32) { float v = src[j]; s = fmaf(v, v, s); }
#pragma unroll
    for (int o = 16; o; o >>= 1) s += __shfl_down_sync(0xffffffffu, s, o);
    if (lane == 0) {
        float r = sqrtf(s);
        if (w < NB) g_w1i[w] = r; else g_w1t[w - NB] = r;
    }
}

__global__ void sgemm_tn(const float* __restrict__ A, const float* __restrict__ Bm,
                         int M, int N, int K) {
    float* C = g_base;
    __shared__ float As[16 * 64];
    __shared__ float Bs[16 * 64];
    int tid = threadIdx.x;
    int tx = tid & 15, ty = tid >> 4;
    int m0 = blockIdx.y * 64, n0 = blockIdx.x * 64;
    int row = tid >> 2, q = tid & 3;
    float acc[4][4] = {};
    for (int k0 = 0; k0 < K; k0 += 16) {
        float4 a = ldg4(A + (size_t)(m0 + row) * K + k0 + q * 4);
        float4 bb = ldg4(Bm + (size_t)(n0 + row) * K + k0 + q * 4);
        As[(q * 4 + 0) * 64 + row] = a.x;  As[(q * 4 + 1) * 64 + row] = a.y;
        As[(q * 4 + 2) * 64 + row] = a.z;  As[(q * 4 + 3) * 64 + row] = a.w;
        Bs[(q * 4 + 0) * 64 + row] = bb.x; Bs[(q * 4 + 1) * 64 + row] = bb.y;
        Bs[(q * 4 + 2) * 64 + row] = bb.z; Bs[(q * 4 + 3) * 64 + row] = bb.w;
        __syncthreads();
#pragma unroll
        for (int k = 0; k < 16; k++) {
            float4 av = *(const float4*)(As + k * 64 + ty * 4);
            float4 bv = *(const float4*)(Bs + k * 64 + tx * 4);
            float aa[4] = {av.x, av.y, av.z, av.w};
            float bw[4] = {bv.x, bv.y, bv.z, bv.w};
#pragma unroll
            for (int ii = 0; ii < 4; ii++)
#pragma unroll
                for (int jj = 0; jj < 4; jj++)
                    acc[ii][jj] = fmaf(aa[ii], bw[jj], acc[ii][jj]);
        }
        __syncthreads();
    }
#pragma unroll
    for (int ii = 0; ii < 4; ii++)
#pragma unroll
        for (int jj = 0; jj < 4; jj++)
            C[(size_t)(m0 + ty * 4 + ii) * N + n0 + tx * 4 + jj] = acc[ii][jj];
}

// per-row Gram, 4x4 register-blocked, symmetric
__global__ void gram_kernel(const float* __restrict__ emb, int ROWS, int which) {
    extern __shared__ float Es[];
    float* out = which ? g_H : g_G;
    int b = blockIdx.x, tid = threadIdx.x;
    int wid = tid >> 5, lane = tid & 31;
    int n = ROWS * ND;
    int np = ROWS * ROWS;
    for (int idx = tid; idx < n; idx += 256) Es[idx] = emb[(size_t)b * n + idx];
    __syncthreads();
    int nt4 = ROWS / 4;
    int count = nt4 * (nt4 + 1) / 2;
    for (int p = wid; p < count; p += 8) {
        int pl = p, tr = 0;
        while (pl >= nt4 - tr) { pl -= nt4 - tr; tr++; }
        int tc = tr + pl;
        const float* E1 = Es + (size_t)tr * 4 * ND;
        const float* E2 = Es + (size_t)tc * 4 * ND;
        float acc[4][4] = {};
        for (int kk = 0; kk < ND; kk += 32) {
            int k = kk + lane;
            float e1[4], e2[4];
#pragma unroll
            for (int j = 0; j < 4; j++) { e1[j] = E1[j * ND + k]; e2[j] = E2[j * ND + k]; }
#pragma unroll
            for (int j = 0; j < 4; j++)
#pragma unroll
                for (int jj = 0; jj < 4; jj++)
                    acc[j][jj] = fmaf(e1[j], e2[jj], acc[j][jj]);
        }
#pragma unroll
        for (int j = 0; j < 4; j++)
#pragma unroll
            for (int jj = 0; jj < 4; jj++) {
#pragma unroll
                for (int o = 16; o; o >>= 1)
                    acc[j][jj] += __shfl_xor_sync(0xffffffffu, acc[j][jj], o);
            }
        if (lane == 0) {
#pragma unroll
            for (int j = 0; j < 4; j++)
#pragma unroll
                for (int jj = 0; jj < 4; jj++) {
                    float v = acc[j][jj];
                    out[(size_t)b * np + (tr * 4 + j) * ROWS + tc * 4 + jj] = v;
                    out[(size_t)b * np + (tc * 4 + jj) * ROWS + tr * 4 + j] = v;
                }
        }
    }
}

// ============================ bf16 cp.async GEMM: BK=64, 3 stages, mid-loop issue ============================
#define BM 128
#define BN 256
#define BK 64
#define ASZW (BM * 36)              /* 4608 words */
#define STGW (ASZW + BN * 36)       /* 13824 words = 55296 B */
#define STAGES 3
#define GEMM_SMEM (STAGES * STGW * 4)   /* 165888 B */

__global__ void __launch_bounds__(256, 1) s_gemm(const __nv_bfloat16* __restrict__ Ah,
                                                 const __nv_bfloat16* __restrict__ Bh,
                                                 float* __restrict__ S) {
    extern __shared__ uint32_t smw[];
    uint32_t sb;
    asm("{ .reg .u64 t; cvta.to.shared.u64 t, %1; cvt.u32.u64 %0, t; }" : "=r"(sb) : "l"(smw));
    const int tid = threadIdx.x;
    const int wid = tid >> 5;
    const int lane = tid & 31;
    const int g = lane >> 2;
    const int t = lane & 3;
    const int wm = wid >> 2;
    const int wn = wid & 3;
    const int by = blockIdx.y;
    const int bx = blockIdx.x;
    const int m0 = by * BM;
    const int n0 = bx * BN;
    const bool pBlk = (bx == 40);
    const bool qBlk = (by >= 72);

    const int r0 = tid >> 3;
    const int c0 = tid & 7;
    const __nv_bfloat16* Agp = (qBlk ? (Ah + (size_t)9216 * ND + (size_t)(by - 72) * BM * ND)
                                     : (Ah + (size_t)m0 * ND)) + (size_t)r0 * ND + c0 * 8;
    const __nv_bfloat16* Bgp = (pBlk ? (Bh + (size_t)10240 * ND)
                                     : (Bh + (size_t)n0 * ND)) + (size_t)r0 * ND + c0 * 8;
    const uint32_t sA = sb + (uint32_t)(r0 * 144 + c0 * 16);
    const uint32_t sB = sb + (uint32_t)(ASZW * 4 + r0 * 144 + c0 * 16);

    const int alr = (lane & 7) + ((lane >> 3) & 1) * 8;
    const int ahf = (lane >> 4) & 1;
    const int blr = (lane & 7) + ((lane >> 4) & 1) * 8;
    const int bhf = (lane >> 3) & 1;
    const uint32_t aFrag = sb + (uint32_t)((wm * 64 + alr) * 144 + ahf * 16);
    const uint32_t bFrag = sb + (uint32_t)(ASZW * 4 + (wn * 64 + blr) * 144 + bhf * 16);

    float cacc[4][8][4];
#pragma unroll
    for (int a = 0; a < 4; a++)
#pragma unroll
        for (int bb = 0; bb < 8; bb++)
#pragma unroll
            for (int cc = 0; cc < 4; cc++) cacc[a][bb][cc] = 0.f;

#define ISSUE_A(stg, kc) do {                                                  \
    uint32_t so = (uint32_t)(stg) * (STGW * 4);                                \
    _Pragma("unroll")                                                          \
    for (int j = 0; j < 4; j++)                                                \
        cpa16(sA + so + j * (32 * 144), Agp + (size_t)j * 32 * ND + (kc));     \
} while (0)
#define ISSUE_B(stg, kc) do {                                                  \
    uint32_t so = (uint32_t)(stg) * (STGW * 4);                                \
    _Pragma("unroll")                                                          \
    for (int j = 0; j < 8; j++)                                                \
        cpa16(sB + so + j * (32 * 144), Bgp + (size_t)j * 32 * ND + (kc));     \
} while (0)

#define COMPUTE(stg, ks) do {                                                  \
    const uint32_t so = (uint32_t)(stg) * (STGW * 4) + (ks) * 32;              \
    uint32_t af[4][4];                                                         \
    uint32_t bf[8][2];                                                         \
    _Pragma("unroll")                                                          \
    for (int mt = 0; mt < 4; mt++)                                             \
        ldsm_x4(af[mt][0], af[mt][1], af[mt][2], af[mt][3],                    \
                aFrag + so + mt * (16 * 144));                                 \
    _Pragma("unroll")                                                          \
    for (int np = 0; np < 4; np++)                                             \
        ldsm_x4(bf[2 * np][0], bf[2 * np][1], bf[2 * np + 1][0],               \
                bf[2 * np + 1][1], bFrag + so + np * (16 * 144));              \
    _Pragma("unroll")                                                          \
    for (int mt = 0; mt < 4; mt++)                                             \
        _Pragma("unroll")                                                      \
        for (int nt = 0; nt < 8; nt++)                                         \
            mma_bf16(cacc[mt][nt], af[mt], bf[nt]);                            \
} while (0)

    ISSUE_A(0, 0);  ISSUE_B(0, 0);
    asm volatile("cp.async.commit_group;" ::: "memory");
    ISSUE_A(1, 64); ISSUE_B(1, 64);
    asm volatile("cp.async.commit_group;" ::: "memory");

#pragma unroll 1
    for (int c = 0; c < 16; c++) {
        asm volatile("cp.async.wait_group 1;" ::: "memory");
        __syncthreads();
        int st = c % 3;
        int nst = (c + 2) % 3;
        int kn = (c + 2) * BK;
        bool more = (c < 14);
        COMPUTE(st, 0);
        if (more) ISSUE_A(nst, kn);
        COMPUTE(st, 1);
        if (more) ISSUE_B(nst, kn);
        COMPUTE(st, 2);
        asm volatile("cp.async.commit_group;" ::: "memory");
        COMPUTE(st, 3);
    }

    if (pBlk && qBlk) return;

    if (!pBlk && !qBlk) {
#pragma unroll
        for (int mt = 0; mt < 4; mt++) {
            int m = m0 + wm * 64 + mt * 16 + g;
#pragma unroll
            for (int nt = 0; nt < 8; nt++) {
                int n = n0 + wn * 64 + nt * 8 + 2 * t;
                float v0 = cacc[mt][nt][0]; v0 = (v0 >= 0.f) ? v0 : 0.1f * v0;
                float v1 = cacc[mt][nt][1]; v1 = (v1 >= 0.f) ? v1 : 0.1f * v1;
                float v2 = cacc[mt][nt][2]; v2 = (v2 >= 0.f) ? v2 : 0.1f * v2;
                float v3 = cacc[mt][nt][3]; v3 = (v3 >= 0.f) ? v3 : 0.1f * v3;
                __stcs(S + (size_t)n * MT + m, v0);
                __stcs(S + (size_t)(n + 1) * MT + m, v1);
                __stcs(S + (size_t)n * MT + m + 8, v2);
                __stcs(S + (size_t)(n + 1) * MT + m + 8, v3);
            }
        }
    } else if (pBlk) {
#pragma unroll
        for (int mt = 0; mt < 4; mt++) {
            int m = m0 + wm * 64 + mt * 16 + g;
#pragma unroll
            for (int nt = 0; nt < 8; nt++) {
                int i = wn * 64 + nt * 8 + 2 * t;
                __stcs(g_P + (size_t)i * MT + m, cacc[mt][nt][0]);
                __stcs(g_P + (size_t)(i + 1) * MT + m, cacc[mt][nt][1]);
                __stcs(g_P + (size_t)i * MT + m + 8, cacc[mt][nt][2]);
                __stcs(g_P + (size_t)(i + 1) * MT + m + 8, cacc[mt][nt][3]);
            }
        }
    } else {
#pragma unroll
        for (int mt = 0; mt < 4; mt++) {
            int b = (by - 72) * BM + wm * 64 + mt * 16 + g;
#pragma unroll
            for (int nt = 0; nt < 8; nt++) {
                int n = n0 + wn * 64 + nt * 8 + 2 * t;
                __stcs(g_Q + (size_t)b * NT + n, cacc[mt][nt][0]);
                __stcs(g_Q + (size_t)b * NT + n + 1, cacc[mt][nt][1]);
                __stcs(g_Q + (size_t)(b + 8) * NT + n, cacc[mt][nt][2]);
                __stcs(g_Q + (size_t)(b + 8) * NT + n + 1, cacc[mt][nt][3]);
            }
        }
    }
#undef ISSUE_A
#undef ISSUE_B
#undef COMPUTE
}

// ============================ per-pair epilogue (R14 proven version, verbatim) ============================
// word offsets: FS 0 (40x37=1480, [l][r]) | Am 1480 (40x44) | Cm 3240 (36x44)
//               Hs 4824 (40x40) | Gs 6424 (36x36) | w2p1 7720 (40x9) | w2p2 8080 (36x10)
#define EPI_WORDS 8440
#define EPI_SMEM (EPI_WORDS * 4)

__global__ void __launch_bounds__(128) pair_epilogue(const float* __restrict__ S,
                                                     float* __restrict__ out) {
    extern __shared__ float sh[];
    __shared__ float Pb[NR], Qi[NL], rnl[NR], cnl[NL], s1s[NL], s2s[NR];
    float* FS = sh;          // [l][r] stride 37
    float* Am = sh + 1480;
    float* Cm = sh + 3240;
    float* Hs = sh + 4824;
    float* Gs = sh + 6424;
    float* w2p1 = sh + 7720;
    float* w2p2 = sh + 8080;
    const int i = blockIdx.x, b = blockIdx.y, tid = threadIdx.x;

    const float* Sp = S + (size_t)i * NL * MT + (size_t)b * NR;
    for (int q = tid; q < 360; q += 128) {
        int l = q / 9, sg = q - l * 9;
        float4 v = ldg4(Sp + (size_t)l * MT + sg * 4);
        float* d = FS + l * 37 + sg * 4;
        d[0] = v.x; d[1] = v.y; d[2] = v.z; d[3] = v.w;
    }
    {
        const float4* Gg = (const float4*)(g_G + (size_t)b * (NR * NR));
        for (int q = tid; q < 324; q += 128) ((float4*)Gs)[q] = Gg[q];
        const float4* Hg = (const float4*)(g_H + (size_t)i * (NL * NL));
        for (int q = tid; q < 400; q += 128) ((float4*)Hs)[q] = Hg[q];
    }
    if (tid < 9) {
        float4 v = ldg4(g_P + (size_t)i * MT + b * NR + tid * 4);
        Pb[tid * 4 + 0] = v.x; Pb[tid * 4 + 1] = v.y;
        Pb[tid * 4 + 2] = v.z; Pb[tid * 4 + 3] = v.w;
    } else if (tid >= 64 && tid < 74) {
        int q = tid - 64;
        float4 v = ldg4(g_Q + (size_t)b * NT + i * NL + q * 4);
        Qi[q * 4 + 0] = v.x; Qi[q * 4 + 1] = v.y;
        Qi[q * 4 + 2] = v.z; Qi[q * 4 + 3] = v.w;
    }
    __syncthreads();

    if (tid < NL) {
        int l = tid; float s = 0.f;
#pragma unroll
        for (int r = 0; r < NR; r++) { float v = FS[l * 37 + r]; s = fmaf(v, v, s); }
        cnl[l] = LAMS / (sqrtf(s) + EPSF);
    } else if (tid >= 64 && tid < 64 + NR) {
        int r = tid - 64; float s = 0.f;
#pragma unroll
        for (int l = 0; l < NL; l++) { float v = FS[l * 37 + r]; s = fmaf(v, v, s); }
        rnl[r] = LAMS / (sqrtf(s) + EPSF);
    }
    __syncthreads();

    for (int idx = tid; idx < NR * NL; idx += 128) {
        int l = idx / NR, r = idx - l * NR;
        float v = FS[l * 37 + r];
        Am[l * 44 + r] = __expf(v * rnl[r]);
        Cm[r * 44 + l] = __expf(v * cnl[l]);
    }
    __syncthreads();

    // fused mini-GEMM + quadratic form: 180 tasks, each a 4x4 tile
    for (int task = tid; task < 180; task += 128) {
        float4 acc0 = make_float4(0.f, 0.f, 0.f, 0.f);
        float4 acc1 = acc0, acc2 = acc0, acc3 = acc0;
        float4 st0 = acc0, st1 = acc0, st2 = acc0, st3 = acc0;
        if (task < 90) {
            int lg = task / 9, rg = task - lg * 9;
            const float* Ab = Am + lg * 4 * 44;
            const float* Gb = Gs + rg * 4;
#pragma unroll
            for (int rp4 = 0; rp4 < 9; rp4++) {
                float4 a0 = *(const float4*)(Ab + rp4 * 4);
                float4 a1 = *(const float4*)(Ab + 44 + rp4 * 4);
                float4 a2 = *(const float4*)(Ab + 88 + rp4 * 4);
                float4 a3 = *(const float4*)(Ab + 132 + rp4 * 4);
                if (rp4 == rg) { st0 = a0; st1 = a1; st2 = a2; st3 = a3; }
                float4 g0 = *(const float4*)(Gb + (rp4 * 4 + 0) * 36);
                float4 g1 = *(const float4*)(Gb + (rp4 * 4 + 1) * 36);
                float4 g2 = *(const float4*)(Gb + (rp4 * 4 + 2) * 36);
                float4 g3 = *(const float4*)(Gb + (rp4 * 4 + 3) * 36);
#define ACC4(ACC, AV)                                                          \
                ACC.x = fmaf(AV.x, g0.x, ACC.x); ACC.y = fmaf(AV.x, g0.y, ACC.y); \
                ACC.z = fmaf(AV.x, g0.z, ACC.z); ACC.w = fmaf(AV.x, g0.w, ACC.w); \
                ACC.x = fmaf(AV.y, g1.x, ACC.x); ACC.y = fmaf(AV.y, g1.y, ACC.y); \
                ACC.z = fmaf(AV.y, g1.z, ACC.z); ACC.w = fmaf(AV.y, g1.w, ACC.w); \
                ACC.x = fmaf(AV.z, g2.x, ACC.x); ACC.y = fmaf(AV.z, g2.y, ACC.y); \
                ACC.z = fmaf(AV.z, g2.z, ACC.z); ACC.w = fmaf(AV.z, g2.w, ACC.w); \
                ACC.x = fmaf(AV.w, g3.x, ACC.x); ACC.y = fmaf(AV.w, g3.y, ACC.y); \
                ACC.z = fmaf(AV.w, g3.z, ACC.z); ACC.w = fmaf(AV.w, g3.w, ACC.w);
                ACC4(acc0, a0) ACC4(acc1, a1) ACC4(acc2, a2) ACC4(acc3, a3)
            }
            int l = lg * 4;
            w2p1[(l + 0) * 9 + rg] = acc0.x * st0.x + acc0.y * st0.y + acc0.z * st0.z + acc0.w * st0.w;
            w2p1[(l + 1) * 9 + rg] = acc1.x * st1.x + acc1.y * st1.y + acc1.z * st1.z + acc1.w * st1.w;
            w2p1[(l + 2) * 9 + rg] = acc2.x * st2.x + acc2.y * st2.y + acc2.z * st2.z + acc2.w * st2.w;
            w2p1[(l + 3) * 9 + rg] = acc3.x * st3.x + acc3.y * st3.y + acc3.z * st3.z + acc3.w * st3.w;
        } else {
            int t2 = task - 90;
            int rg = t2 / 10, lg = t2 - rg * 10;
            const float* Cb = Cm + rg * 4 * 44;
            const float* Hb = Hs + lg * 4;
#pragma unroll
            for (int lp4 = 0; lp4 < 10; lp4++) {
                float4 a0 = *(const float4*)(Cb + lp4 * 4);
                float4 a1 = *(const float4*)(Cb + 44 + lp4 * 4);
                float4 a2 = *(const float4*)(Cb + 88 + lp4 * 4);
                float4 a3 = *(const float4*)(Cb + 132 + lp4 * 4);
                if (lp4 == lg) { st0 = a0; st1 = a1; st2 = a2; st3 = a3; }
                float4 g0 = *(const float4*)(Hb + (lp4 * 4 + 0) * 40);
                float4 g1 = *(const float4*)(Hb + (lp4 * 4 + 1) * 40);
                float4 g2 = *(const float4*)(Hb + (lp4 * 4 + 2) * 40);
                float4 g3 = *(const float4*)(Hb + (lp4 * 4 + 3) * 40);
                ACC4(acc0, a0) ACC4(acc1, a1) ACC4(acc2, a2) ACC4(acc3, a3)
#undef ACC4
            }
            int r = rg * 4;
            w2p2[(r + 0) * 10 + lg] = acc0.x * st0.x + acc0.y * st0.y + acc0.z * st0.z + acc0.w * st0.w;
            w2p2[(r + 1) * 10 + lg] = acc1.x * st1.x + acc1.y * st1.y + acc1.z * st1.z + acc1.w * st1.w;
            w2p2[(r + 2) * 10 + lg] = acc2.x * st2.x + acc2.y * st2.y + acc2.z * st2.z + acc2.w * st2.w;
            w2p2[(r + 3) * 10 + lg] = acc3.x * st3.x + acc3.y * st3.y + acc3.z * st3.z + acc3.w * st3.w;
        }
    }
    __syncthreads();

    if (tid < NL) {
        int l = tid; float w12 = 0.f, w2 = 0.f;
#pragma unroll
        for (int r = 0; r < NR; r++) w12 = fmaf(Am[l * 44 + r], Pb[r], w12);
#pragma unroll
        for (int k = 0; k < 9; k++) w2 += w2p1[l * 9 + k];
        float den = fmaxf(g_w1t[i] * sqrtf(fmaxf(w2, 0.f)), EPSF);
        s1s[l] = __fdividef(w12, den);
    } else if (tid >= 64 && tid < 64 + NR) {
        int r = tid - 64; float w12 = 0.f, w2 = 0.f;
#pragma unroll
        for (int l = 0; l < NL; l++) w12 = fmaf(Cm[r * 44 + l], Qi[l], w12);
#pragma unroll
        for (int k = 0; k < 10; k++) w2 += w2p2[r * 10 + k];
        float den = fmaxf(g_w1i[b] * sqrtf(fmaxf(w2, 0.f)), EPSF);
        s2s[r] = __fdividef(w12, den);
    }
    __syncthreads();

    if (tid == 0) {
        float m1 = 0.f, m2 = 0.f;
#pragma unroll
        for (int l = 0; l < NL; l++) m1 += s1s[l];
#pragma unroll
        for (int r = 0; r < NR; r++) m2 += s2s[r];
        out[(size_t)b * NB + i] = g_base[b * NB + i] + m1 * (1.f / NL) + m2 * (1.f / NR);
    }
}

// ============================ launch ============================
extern "C" void kernel_launch(void* const* d_in, const int* in_sizes, int n_in,
                              void* d_out, int out_size) {
    (void)in_sizes; (void)n_in; (void)out_size;
    const float* pool_img = (const float*)d_in[0];
    const float* img_emb  = (const float*)d_in[1];
    const float* pool_txt = (const float*)d_in[2];
    const float* cap_emb  = (const float*)d_in[3];
    float* out = (float*)d_out;

    cudaFuncSetAttribute((const void*)gram_kernel,
                         cudaFuncAttributeMaxDynamicSharedMemorySize, NL * ND * 4);
    cudaFuncSetAttribute((const void*)s_gemm,
                         cudaFuncAttributeMaxDynamicSharedMemorySize, GEMM_SMEM);
    cudaFuncSetAttribute((const void*)pair_epilogue,
                         cudaFuncAttributeMaxDynamicSharedMemorySize, EPI_SMEM);

    float* dS = nullptr;
    cudaGetSymbolAddress((void**)&dS, g_S);
    __nv_bfloat16* dAh = nullptr; cudaGetSymbolAddress((void**)&dAh, g_Ah);
    __nv_bfloat16* dBh = nullptr; cudaGetSymbolAddress((void**)&dBh, g_Bh);

    // order: s_gemm stays at launch index 3 (profiled slot)
    cvt_kernel<<<9984, 256>>>(img_emb, pool_img, cap_emb, pool_txt);
    gram_kernel<<<NB, 256, NR * ND * 4>>>(img_emb, NR, 0);
    gram_kernel<<<NB, 256, NL * ND * 4>>>(cap_emb, NL, 1);
    s_gemm<<<dim3(41, 74), 256, GEMM_SMEM>>>(dAh, dBh, dS);
    norm_kernel<<<64, 256>>>(pool_img, pool_txt);
    sgemm_tn<<<dim3(NB / 64, NB / 64), 256>>>(pool_img, pool_txt, NB, NB, ND);
    pair_epilogue<<<dim3(NB, NB), 128, EPI_SMEM>>>(dS, out);
}